// round 3
// baseline (speedup 1.0000x reference)
#include <cuda_runtime.h>

// loss = 0.5 * mean( (tw[b,j] * (output[b,j,hw] - target[b,j,hw]))^2 )
// B=256, J=17, HW=64*48=3072  ->  N = 13,369,344 floats, N4 = 3,342,336 float4
// tw has B*J = 4352 entries; each covers 768 consecutive float4s.
//
// Single fused kernel: grid-stride weighted-SSE, block partials to a
// __device__ scratch array, last-block-done finalization (deterministic:
// fixed-order double accumulation by exactly one block).

#define N_ELEMS   13369344
#define N4        3342336
#define F4_PER_BJ 768
#define NBLOCKS   1184      // 148 SMs * 8
#define NTHREADS  256

__device__ float        g_partials[NBLOCKS];
__device__ unsigned int g_count;   // zero-initialized; reset by last block each call

__global__ __launch_bounds__(NTHREADS) void wmse_fused_kernel(
    const float4* __restrict__ out4,
    const float4* __restrict__ tgt4,
    const float*  __restrict__ tw,
    float*        __restrict__ result)
{
    const int tid    = threadIdx.x;
    const int stride = gridDim.x * blockDim.x;
    int i = blockIdx.x * blockDim.x + tid;

    float acc = 0.0f;
    for (; i < N4; i += stride) {
        const float4 o = out4[i];
        const float4 t = tgt4[i];
        const float  w = tw[i / F4_PER_BJ];   // 4352 entries, L1/L2-resident
        float d0 = (o.x - t.x) * w;
        float d1 = (o.y - t.y) * w;
        float d2 = (o.z - t.z) * w;
        float d3 = (o.w - t.w) * w;
        acc += d0 * d0 + d1 * d1 + d2 * d2 + d3 * d3;
    }

    // intra-block reduce
    #pragma unroll
    for (int off = 16; off > 0; off >>= 1)
        acc += __shfl_down_sync(0xFFFFFFFFu, acc, off);

    __shared__ float warp_sums[NTHREADS / 32];
    if ((tid & 31) == 0) warp_sums[tid >> 5] = acc;
    __syncthreads();

    if (tid == 0) {
        float v = 0.0f;
        #pragma unroll
        for (int w = 0; w < NTHREADS / 32; w++) v += warp_sums[w];
        g_partials[blockIdx.x] = v;
    }

    // last-block-done finalization
    __shared__ bool is_last;
    if (tid == 0) {
        __threadfence();
        unsigned int prev = atomicAdd(&g_count, 1u);
        is_last = (prev == (unsigned int)(NBLOCKS - 1));
    }
    __syncthreads();

    if (is_last) {
        // deterministic: exactly one block, fixed iteration order per thread,
        // double accumulation (1184 partials, ~5 per thread)
        double dacc = 0.0;
        for (int j = tid; j < NBLOCKS; j += NTHREADS)
            dacc += (double)g_partials[j];

        #pragma unroll
        for (int off = 16; off > 0; off >>= 1)
            dacc += __shfl_down_sync(0xFFFFFFFFu, dacc, off);

        __shared__ double dwarp[NTHREADS / 32];
        if ((tid & 31) == 0) dwarp[tid >> 5] = dacc;
        __syncthreads();

        if (tid == 0) {
            double total = 0.0;
            #pragma unroll
            for (int w = 0; w < NTHREADS / 32; w++) total += dwarp[w];
            result[0] = (float)(0.5 * total / (double)N_ELEMS);
            g_count = 0;   // reset for next graph replay
        }
    }
}

extern "C" void kernel_launch(void* const* d_in, const int* in_sizes, int n_in,
                              void* d_out, int out_size)
{
    const float4* out4 = (const float4*)d_in[0];
    const float4* tgt4 = (const float4*)d_in[1];
    const float*  tw   = (const float*)d_in[2];
    float* out = (float*)d_out;

    wmse_fused_kernel<<<NBLOCKS, NTHREADS>>>(out4, tgt4, tw, out);
}

// round 4
// speedup vs baseline: 1.1216x; 1.1216x over previous
#include <cuda_runtime.h>

// loss = 0.5 * mean( (tw[b,j] * (output[b,j,hw] - target[b,j,hw]))^2 )
// B=256, J=17, HW=64*48=3072  ->  N = 13,369,344 floats, N4 = 3,342,336 float4
// tw has B*J = 4352 entries; each covers 768 consecutive float4s.
//
// Two kernels in the graph:
//   1) wmse_partial: grid-stride weighted-SSE -> 1184 block partials (at LTS ceiling)
//   2) wmse_final:   1 warp, fixed-order double reduce of 1184 partials,
//                    launched with PDL so its setup overlaps kernel 1's tail.

#define N_ELEMS   13369344
#define N4        3342336
#define F4_PER_BJ 768
#define NBLOCKS   1184      // 148 SMs * 8;  1184 = 32 * 37
#define NTHREADS  256

__device__ float g_partials[NBLOCKS];

__global__ __launch_bounds__(NTHREADS) void wmse_partial_kernel(
    const float4* __restrict__ out4,
    const float4* __restrict__ tgt4,
    const float*  __restrict__ tw)
{
    const int tid    = threadIdx.x;
    const int stride = gridDim.x * blockDim.x;
    int i = blockIdx.x * blockDim.x + tid;

    float acc = 0.0f;
    for (; i < N4; i += stride) {
        const float4 o = out4[i];
        const float4 t = tgt4[i];
        const float  w = tw[i / F4_PER_BJ];   // 4352 entries, L1/L2-resident
        float d0 = (o.x - t.x) * w;
        float d1 = (o.y - t.y) * w;
        float d2 = (o.z - t.z) * w;
        float d3 = (o.w - t.w) * w;
        acc += d0 * d0 + d1 * d1 + d2 * d2 + d3 * d3;
    }

    // intra-block reduce
    #pragma unroll
    for (int off = 16; off > 0; off >>= 1)
        acc += __shfl_down_sync(0xFFFFFFFFu, acc, off);

    __shared__ float warp_sums[NTHREADS / 32];
    if ((tid & 31) == 0) warp_sums[tid >> 5] = acc;
    __syncthreads();

    if (tid == 0) {
        float v = 0.0f;
        #pragma unroll
        for (int w = 0; w < NTHREADS / 32; w++) v += warp_sums[w];
        g_partials[blockIdx.x] = v;
    }
}

// Single-warp finalize: 1184 = 32 lanes * 37 partials each, fixed order,
// double accumulation -> deterministic.
__global__ __launch_bounds__(32) void wmse_final_kernel(float* __restrict__ out)
{
#if __CUDA_ARCH__ >= 900
    cudaGridDependencySynchronize();   // PDL: wait for partial kernel completion
#endif
    const int lane = threadIdx.x;

    double acc = 0.0;
    #pragma unroll
    for (int k = 0; k < NBLOCKS / 32; k++)
        acc += (double)g_partials[lane + k * 32];

    #pragma unroll
    for (int off = 16; off > 0; off >>= 1)
        acc += __shfl_down_sync(0xFFFFFFFFu, acc, off);

    if (lane == 0)
        out[0] = (float)(0.5 * acc / (double)N_ELEMS);
}

extern "C" void kernel_launch(void* const* d_in, const int* in_sizes, int n_in,
                              void* d_out, int out_size)
{
    const float4* out4 = (const float4*)d_in[0];
    const float4* tgt4 = (const float4*)d_in[1];
    const float*  tw   = (const float*)d_in[2];
    float* out = (float*)d_out;

    wmse_partial_kernel<<<NBLOCKS, NTHREADS>>>(out4, tgt4, tw);

    // Finalize with programmatic dependent launch so its setup overlaps the
    // partial kernel's tail; fall back to a plain launch if unsupported.
    cudaLaunchConfig_t cfg = {};
    cfg.gridDim  = dim3(1, 1, 1);
    cfg.blockDim = dim3(32, 1, 1);
    cfg.dynamicSmemBytes = 0;
    cfg.stream = 0;
    cudaLaunchAttribute attrs[1];
    attrs[0].id = cudaLaunchAttributeProgrammaticStreamSerialization;
    attrs[0].val.programmaticStreamSerializationAllowed = 1;
    cfg.attrs = attrs;
    cfg.numAttrs = 1;

    cudaError_t err = cudaLaunchKernelEx(&cfg, wmse_final_kernel, out);
    if (err != cudaSuccess) {
        (void)cudaGetLastError();      // clear sticky error state
        wmse_final_kernel<<<1, 32>>>(out);
    }
}

// round 7
// speedup vs baseline: 1.4068x; 1.2542x over previous
#include <cuda_runtime.h>

// loss = 0.5 * mean( (tw[b,j] * (output[b,j,hw] - target[b,j,hw]))^2 )
// B=256, J=17, HW=64*48=3072  ->  N = 13,369,344 floats, N4 = 3,342,336 float4
// tw has B*J = 4352 entries; each covers 768 consecutive float4s.
//
// SINGLE kernel. Block partials are accumulated into one 64-bit fixed-point
// accumulator (scale 2^40) via atomicAdd(ull) -> integer adds are associative,
// so the result is bitwise deterministic regardless of block arrival order.
// The last-arriving block does atomicExch (read+reset), scales, writes out.

#define N_ELEMS   13369344
#define N4        3342336
#define F4_PER_BJ 768
#define NBLOCKS   1184      // 148 SMs * 8 CTAs (64 warps/SM, full occupancy)
#define NTHREADS  256

__device__ unsigned long long g_sum;    // zero-init; reset via atomicExch each call
__device__ unsigned int       g_count;  // zero-init; reset by last block each call

__global__ __launch_bounds__(NTHREADS) void wmse_onepass_kernel(
    const float4* __restrict__ out4,
    const float4* __restrict__ tgt4,
    const float*  __restrict__ tw,
    float*        __restrict__ result)
{
    const int tid    = threadIdx.x;
    const int stride = gridDim.x * blockDim.x;
    int i = blockIdx.x * blockDim.x + tid;

    float acc = 0.0f;
    for (; i < N4; i += stride) {
        const float4 o = out4[i];
        const float4 t = tgt4[i];
        const float  w = tw[i / F4_PER_BJ];   // 4352 entries, L1/L2-resident
        float d0 = (o.x - t.x) * w;
        float d1 = (o.y - t.y) * w;
        float d2 = (o.z - t.z) * w;
        float d3 = (o.w - t.w) * w;
        acc += d0 * d0 + d1 * d1 + d2 * d2 + d3 * d3;
    }

    // intra-block reduce (float, fixed order)
    #pragma unroll
    for (int off = 16; off > 0; off >>= 1)
        acc += __shfl_down_sync(0xFFFFFFFFu, acc, off);

    __shared__ float warp_sums[NTHREADS / 32];
    if ((tid & 31) == 0) warp_sums[tid >> 5] = acc;
    __syncthreads();

    __shared__ bool is_last;
    if (tid == 0) {
        float v = 0.0f;
        #pragma unroll
        for (int w = 0; w < NTHREADS / 32; w++) v += warp_sums[w];

        // fixed-point (2^40) contribution -> associative integer accumulation
        unsigned long long q =
            (unsigned long long)((double)v * 1099511627776.0);  // * 2^40
        atomicAdd(&g_sum, q);
        __threadfence();  // order value-add before counter-add (cross-addr)
        unsigned int prev = atomicAdd(&g_count, 1u);
        is_last = (prev == (unsigned int)(NBLOCKS - 1));
    }
    __syncthreads();

    if (is_last && tid == 0) {
        // read + reset in one atomic; all contributions are visible because
        // every block fenced its value-add before the counter-add we observed
        unsigned long long total_q = atomicExch(&g_sum, 0ULL);
        double total = (double)total_q * 9.094947017729282379e-13;  // * 2^-40
        result[0] = (float)(0.5 * total / (double)N_ELEMS);
        g_count = 0;   // safe: this block was the final incrementer
    }
}

extern "C" void kernel_launch(void* const* d_in, const int* in_sizes, int n_in,
                              void* d_out, int out_size)
{
    const float4* out4 = (const float4*)d_in[0];
    const float4* tgt4 = (const float4*)d_in[1];
    const float*  tw   = (const float*)d_in[2];
    float* out = (float*)d_out;

    wmse_onepass_kernel<<<NBLOCKS, NTHREADS>>>(out4, tgt4, tw, out);
}